// round 17
// baseline (speedup 1.0000x reference)
#include <cuda_runtime.h>
#include <cuda_bf16.h>
#include <cstdint>

// Problem constants (fixed by the dataset)
#define BB 4
#define LL 1024
#define HH 32
#define WW 32
#define CC 768
#define NN 16
#define DR 48
#define KK 4
#define MTOT (BB*LL)          // 4096
#define DBLC (DR + 2*NN)      // 80

// ---------------- scratch (no allocations allowed) ----------------
__device__ __nv_bfloat16 g_xn16[MTOT*CC];
__device__ float         g_xz  [2][MTOT*2*CC];
__device__ float         g_uc  [2][MTOT*CC];
__device__ __nv_bfloat16 g_uc16[2][MTOT*CC];
__device__ float         g_dbl [2][MTOT*DBLC];
__device__ __nv_bfloat16 g_dbl16[2][MTOT*DBLC];
__device__ float         g_dt  [2][MTOT*CC];
__device__ __nv_bfloat16 g_y16 [2][MTOT*CC];
__device__ __nv_bfloat16 g_fused16[MTOT*2*CC];
__device__ __nv_bfloat16 g_h16 [MTOT*CC];
__device__ int g_idx_cw [LL];
__device__ int g_idx_ccw[LL];
// bf16 transposed weights Wt[n][k]
__device__ __nv_bfloat16 g_inwt [2][2*CC*CC];
__device__ __nv_bfloat16 g_xpt  [2][DBLC*CC];
__device__ __nv_bfloat16 g_dtpt [2][CC*DR];
__device__ __nv_bfloat16 g_outwt[2][CC*CC];
__device__ __nv_bfloat16 g_fw1t [CC*2*CC];
__device__ __nv_bfloat16 g_fw2t [CC*CC];

// ---------------- spiral index generation ----------------
__global__ void spiral_idx_kernel(int* idx_cw, int* idx_ccw) {
    int cell = threadIdx.x;
    int i = cell / WW, j = cell % WW;
    int r = min(min(i, j), min(HH - 1 - i, WW - 1 - j));
    int h = HH - 2 * r, w = WW - 2 * r;
    int prior = HH * WW - h * w;
    int pos;
    if (i == r)                pos = j - r;
    else if (j == WW - 1 - r)  pos = (w - 1) + (i - r);
    else if (i == HH - 1 - r)  pos = (w - 1) + (h - 1) + (WW - 1 - r - j);
    else                       pos = 2*(w - 1) + (h - 1) + (HH - 1 - r - i);
    idx_cw[prior + pos] = cell;
    if (i == r)                pos = (WW - 1 - r) - j;
    else if (j == r)           pos = (w - 1) + (i - r);
    else if (i == HH - 1 - r)  pos = (w - 1) + (h - 1) + (j - r);
    else                       pos = 2*(w - 1) + (h - 1) + (HH - 1 - r - i);
    idx_ccw[prior + pos] = cell;
}

// ---------------- weight transpose+convert: in[K][N] f32 -> out[N][K] bf16 ----------------
struct WDesc { const float* in; __nv_bfloat16* out; int K; int N; };
struct WAll { WDesc w[10]; };
__global__ void wt_kernel(WAll all) {
    WDesc d = all.w[blockIdx.z];
    int n0 = blockIdx.x * 32, k0 = blockIdx.y * 32;
    if (n0 >= d.N || k0 >= d.K) return;
    __shared__ float t[32][33];
    int tx = threadIdx.x, ty = threadIdx.y;          // 32 x 8
#pragma unroll
    for (int i = 0; i < 32; i += 8) {
        int k = k0 + ty + i, n = n0 + tx;
        t[ty + i][tx] = (k < d.K && n < d.N) ? d.in[(size_t)k * d.N + n] : 0.f;
    }
    __syncthreads();
#pragma unroll
    for (int i = 0; i < 32; i += 8) {
        int n = n0 + ty + i, k = k0 + tx;
        if (n < d.N && k < d.K) d.out[(size_t)n * d.K + k] = __float2bfloat16(t[tx][ty + i]);
    }
}

// ---------------- layernorm -> bf16 ----------------
__global__ void layernorm_kernel(const float* __restrict__ x,
                                 const float* __restrict__ w,
                                 const float* __restrict__ b) {
    int row = blockIdx.x;
    const float* xr = x + (size_t)row * CC;
    float s = 0.f, s2 = 0.f;
    for (int c = threadIdx.x; c < CC; c += 256) {
        float v = xr[c];
        s += v; s2 += v * v;
    }
    __shared__ float sh_s[8], sh_s2[8];
    for (int o = 16; o > 0; o >>= 1) {
        s  += __shfl_xor_sync(0xffffffffu, s,  o);
        s2 += __shfl_xor_sync(0xffffffffu, s2, o);
    }
    int warp = threadIdx.x >> 5, lane = threadIdx.x & 31;
    if (lane == 0) { sh_s[warp] = s; sh_s2[warp] = s2; }
    __syncthreads();
    if (warp == 0) {
        s  = (lane < 8) ? sh_s[lane]  : 0.f;
        s2 = (lane < 8) ? sh_s2[lane] : 0.f;
        for (int o = 4; o > 0; o >>= 1) {
            s  += __shfl_xor_sync(0xffffffffu, s,  o);
            s2 += __shfl_xor_sync(0xffffffffu, s2, o);
        }
        if (lane == 0) { sh_s[0] = s; sh_s2[0] = s2; }
    }
    __syncthreads();
    float mu  = sh_s[0] * (1.f / CC);
    float var = sh_s2[0] * (1.f / CC) - mu * mu;
    float inv = rsqrtf(var + 1e-6f);
    for (int c = threadIdx.x; c < CC; c += 256)
        g_xn16[(size_t)row * CC + c] = __float2bfloat16((xr[c] - mu) * inv * w[c] + b[c]);
}

// ---------------- bf16 tensor-core GEMM: BK=64, 3-stage, 1 sync/tile ----------------
// BM=BN=128, BK=64, 256 threads, warp grid 2x4, warp tile 64x32, m16n8k16 bf16
#define APk 72                 // smem pitch in bf16 elems (144 B): rows stride 16B mod 128
#define STGE (128*APk)         // elems per stage per matrix (9216)
#define NSTG 3
#define STGB (2*STGE*2)        // bytes per stage (A then B) = 36864
#define GEMM_SMEM (NSTG*STGB)  // 110592

struct BrArgs {
    const __nv_bfloat16* A;
    const __nv_bfloat16* Wt;       // [n][k]
    const float* bias;
    float* out32;
    __nv_bfloat16* out16;
    const int* a_perm;
    const int* o_perm;
    int o_coloff;
};

__device__ __forceinline__ void cp16(uint32_t dst, const void* src, int sz) {
    asm volatile("cp.async.cg.shared.global [%0], [%1], 16, %2;\n"
                 :: "r"(dst), "l"(src), "r"(sz));
}
__device__ __forceinline__ void ldsm4(uint32_t addr, uint32_t& r0, uint32_t& r1,
                                      uint32_t& r2, uint32_t& r3) {
    asm volatile("ldmatrix.sync.aligned.m8n8.x4.shared.b16 {%0,%1,%2,%3}, [%4];"
                 : "=r"(r0), "=r"(r1), "=r"(r2), "=r"(r3) : "r"(addr));
}

__global__ __launch_bounds__(256, 2)
void bf16gemm_kernel(BrArgs P0, BrArgs P1, int lda, int ldo, int Nn, int Kk,
                     int act, const float* __restrict__ resid) {
    BrArgs P = (blockIdx.z == 0) ? P0 : P1;
    extern __shared__ __nv_bfloat16 smem[];
    int tid = threadIdx.x;
    int row0 = blockIdx.y * 128, col0 = blockIdx.x * 128;
    int warp = tid >> 5, lane = tid & 31;
    int wm = warp >> 2, wn = warp & 3;
    int g = lane >> 2, t4 = lane & 3;

    // ---- loader mapping: each thread owns one row-slot, one 32-elem k-half (4x16B)
    int lrow = tid >> 1;                 // 0..127
    int kc = (tid & 1) * 32;
    int garow = row0 + lrow;
    if (P.a_perm) garow = (garow & ~(LL - 1)) + P.a_perm[garow & (LL - 1)];
    const __nv_bfloat16* abase = P.A + (size_t)garow * lda;
    int gn = col0 + lrow;
    const __nv_bfloat16* bbase = P.Wt + (size_t)(gn < Nn ? gn : 0) * Kk;
    bool bok = (gn < Nn);

    uint32_t sbase = (uint32_t)__cvta_generic_to_shared(smem);
    uint32_t aoff = (lrow * APk + kc) * 2;

    // ---- ldmatrix lane offsets (within a stage)
    uint32_t a_off[4], b_off[2];
    {
        int arl = lane & 15, akhi = (lane >> 4) << 3;
#pragma unroll
        for (int mi = 0; mi < 4; mi++)
            a_off[mi] = ((wm * 64 + mi * 16 + arl) * APk + akhi) * 2;
        int bnr = ((lane >> 4) << 3) + (lane & 7);
        int bkhi = ((lane >> 3) & 1) << 3;
#pragma unroll
        for (int np = 0; np < 2; np++)
            b_off[np] = ((wn * 32 + np * 16 + bnr) * APk + bkhi) * 2;
    }

    float acc[4][4][4];
#pragma unroll
    for (int i = 0; i < 4; i++)
#pragma unroll
        for (int j = 0; j < 4; j++)
#pragma unroll
            for (int q = 0; q < 4; q++) acc[i][j][q] = 0.f;

    int ntiles = (Kk + 63) >> 6;

    auto issue = [&](int t) {
        if (t < ntiles) {
            uint32_t sg = sbase + (uint32_t)(t % NSTG) * STGB;
            int k0 = t * 64 + kc;
#pragma unroll
            for (int c = 0; c < 4; c++) {
                int kb = k0 + c * 8;
                int sa = (kb < Kk) ? 16 : 0;
                cp16(sg + aoff + c * 16, abase + kb, sa);
                cp16(sg + STGE*2 + aoff + c * 16, bbase + kb, bok ? sa : 0);
            }
        }
        asm volatile("cp.async.commit_group;\n");
    };

    issue(0); issue(1);

    for (int t = 0; t < ntiles; t++) {
        asm volatile("cp.async.wait_group 1;\n");
        __syncthreads();
        issue(t + 2);     // stage (t+2)%3 == (t-1)%3: consumed at iter t-1, safe after sync
        uint32_t abuf = sbase + (uint32_t)(t % NSTG) * STGB;
        uint32_t bbuf = abuf + STGE*2;
        // process 4 k16-halves, batched in pairs of 2
#pragma unroll
        for (int kp = 0; kp < 2; kp++) {
            uint32_t af[2][4][4], bf[2][4][2];
#pragma unroll
            for (int kh = 0; kh < 2; kh++) {
                uint32_t ko = (kp * 2 + kh) * 32;   // 16 elems = 32 bytes per k16
#pragma unroll
                for (int mi = 0; mi < 4; mi++)
                    ldsm4(abuf + ko + a_off[mi],
                          af[kh][mi][0], af[kh][mi][1], af[kh][mi][2], af[kh][mi][3]);
#pragma unroll
                for (int np = 0; np < 2; np++)
                    ldsm4(bbuf + ko + b_off[np],
                          bf[kh][2*np][0], bf[kh][2*np][1],
                          bf[kh][2*np+1][0], bf[kh][2*np+1][1]);
            }
#pragma unroll
            for (int kh = 0; kh < 2; kh++)
#pragma unroll
                for (int mi = 0; mi < 4; mi++)
#pragma unroll
                    for (int ni = 0; ni < 4; ni++)
                        asm volatile(
                            "mma.sync.aligned.m16n8k16.row.col.f32.bf16.bf16.f32 "
                            "{%0,%1,%2,%3}, {%4,%5,%6,%7}, {%8,%9}, {%0,%1,%2,%3};\n"
                            : "+f"(acc[mi][ni][0]), "+f"(acc[mi][ni][1]),
                              "+f"(acc[mi][ni][2]), "+f"(acc[mi][ni][3])
                            : "r"(af[kh][mi][0]), "r"(af[kh][mi][1]),
                              "r"(af[kh][mi][2]), "r"(af[kh][mi][3]),
                              "r"(bf[kh][ni][0]), "r"(bf[kh][ni][1]));
        }
    }

    // ---- epilogue
#pragma unroll
    for (int mi = 0; mi < 4; mi++) {
#pragma unroll
        for (int half = 0; half < 2; half++) {
            int grow = row0 + wm * 64 + mi * 16 + g + half * 8;
            int orow = grow;
            if (P.o_perm) orow = (grow & ~(LL - 1)) + P.o_perm[grow & (LL - 1)];
#pragma unroll
            for (int ni = 0; ni < 4; ni++) {
                int gc = col0 + wn * 32 + ni * 8 + 2 * t4;
                if (gc >= Nn) continue;
                float v0 = acc[mi][ni][half * 2 + 0];
                float v1 = acc[mi][ni][half * 2 + 1];
                if (P.bias) { v0 += P.bias[gc]; v1 += P.bias[gc + 1]; }
                if (act == 1) {                       // exact GELU
                    v0 = 0.5f * v0 * (1.f + erff(v0 * 0.70710678118654752f));
                    v1 = 0.5f * v1 * (1.f + erff(v1 * 0.70710678118654752f));
                } else if (act == 2) {                // softplus
                    v0 = (v0 > 20.f) ? v0 : log1pf(expf(v0));
                    v1 = (v1 > 20.f) ? v1 : log1pf(expf(v1));
                }
                if (resid) {
                    v0 += resid[(size_t)grow * Nn + gc];
                    v1 += resid[(size_t)grow * Nn + gc + 1];
                }
                size_t oidx = (size_t)orow * ldo + P.o_coloff + gc;
                if (P.out32) *(float2*)(P.out32 + oidx) = make_float2(v0, v1);
                if (P.out16) *(__nv_bfloat162*)(P.out16 + oidx) = __floats2bfloat162_rn(v0, v1);
            }
        }
    }
}

// ---------------- causal depthwise conv (K=4) + SiLU, dual-branch ----------------
__global__ void conv_silu_kernel(const float* __restrict__ cw0, const float* __restrict__ cb0,
                                 const float* __restrict__ cw1, const float* __restrict__ cb1) {
    int br = blockIdx.y;
    const float* xz = g_xz[br];
    const float* cw = br ? cw1 : cw0;
    const float* cb = br ? cb1 : cb0;
    int t = blockIdx.x * blockDim.x + threadIdx.x;
    if (t >= MTOT * CC) return;
    int d = t % CC;
    int m = t / CC;
    int l = m & (LL - 1);
    float acc = cb[d];
#pragma unroll
    for (int k = 0; k < KK; k++) {
        int ls = l - (KK - 1) + k;
        if (ls >= 0) acc = fmaf(cw[d * KK + k],
                                xz[(size_t)(m - (KK - 1) + k) * (2 * CC) + d], acc);
    }
    float s = 1.f / (1.f + __expf(-acc));
    float v = acc * s;
    g_uc[br][t] = v;
    g_uc16[br][t] = __float2bfloat16(v);
}

// ---------------- selective scan: smem-staged cp.async pipeline ----------------
#define ST 64
#define SROW 56
__global__ __launch_bounds__(128)
void scan_kernel(const float* __restrict__ A0, const float* __restrict__ D0,
                 const float* __restrict__ A1, const float* __restrict__ D1) {
    int br = blockIdx.y;
    int b  = blockIdx.x / (CC / 8);
    int d0 = (blockIdx.x % (CC / 8)) * 8;
    const float* __restrict__ dt  = g_dt[br];
    const float* __restrict__ dbl = g_dbl[br];
    const float* __restrict__ uc  = g_uc[br];
    const float* __restrict__ xz  = g_xz[br];
    const float* Alog = br ? A1 : A0;
    const float* Dp   = br ? D1 : D0;
    int tid = threadIdx.x;
    int ch = tid >> 4;            // 0..7
    int n  = tid & 15;
    int d  = d0 + ch;
    float a  = -expf(Alog[d * NN + n]);
    float Dv = Dp[d];
    size_t mbase = (size_t)b * LL;

    __shared__ float sbuf[2][ST * SROW];
    uint32_t sb = (uint32_t)__cvta_generic_to_shared(sbuf);

    const float* dtB = dt  + mbase * CC + d0;
    const float* ucB = uc  + mbase * CC + d0;
    const float* bcB = dbl + mbase * DBLC + DR;
    const float* zB  = xz  + mbase * 2 * CC + CC + d0;
    __nv_bfloat16* yB = g_y16[br] + mbase * CC + d;

    auto issue = [&](int c) {
        int l0 = c * ST;
        uint32_t dstb = sb + (uint32_t)(c & 1) * (ST * SROW * 4);
        for (int j = tid; j < ST * 14; j += 128) {
            int ll = j / 14, piece = j % 14;
            int l = l0 + ll;
            uint32_t dst = dstb + (uint32_t)(ll * SROW + piece * 4) * 4;
            const float* src;
            if (piece < 2)       src = dtB + (size_t)l * CC   + piece * 4;
            else if (piece < 4)  src = ucB + (size_t)l * CC   + (piece - 2) * 4;
            else if (piece < 12) src = bcB + (size_t)l * DBLC + (piece - 4) * 4;
            else                 src = zB  + (size_t)l * 2*CC + (piece - 12) * 4;
            cp16(dst, src, 16);
        }
        asm volatile("cp.async.commit_group;\n");
    };

    issue(0);
    float h = 0.f;
    const int NCH = LL / ST;      // 16
    for (int c = 0; c < NCH; c++) {
        if (c + 1 < NCH) issue(c + 1);
        else asm volatile("cp.async.commit_group;\n");
        asm volatile("cp.async.wait_group 1;\n");
        __syncthreads();
        const float* s = sbuf[c & 1];
        int l0 = c * ST;
#pragma unroll 4
        for (int ll = 0; ll < ST; ll++) {
            const float* row = s + ll * SROW;
            float dtv = row[ch];
            float uv  = row[8 + ch];
            float bv  = row[16 + n];
            float cv  = row[32 + n];
            float dA = __expf(dtv * a);
            h = fmaf(h, dA, dtv * bv * uv);
            float yp = h * cv;
            yp += __shfl_xor_sync(0xffffffffu, yp, 1);
            yp += __shfl_xor_sync(0xffffffffu, yp, 2);
            yp += __shfl_xor_sync(0xffffffffu, yp, 4);
            yp += __shfl_xor_sync(0xffffffffu, yp, 8);
            if (n == 0) {
                float zv = row[48 + ch];
                float sz = zv / (1.f + __expf(-zv));
                yB[(size_t)(l0 + ll) * CC] = __float2bfloat16((yp + Dv * uv) * sz);
            }
        }
        __syncthreads();
    }
}

// ---------------- host side ----------------
template <typename T> static T* sym(const void* s) {
    void* p = nullptr; cudaGetSymbolAddress(&p, s); return (T*)p;
}

extern "C" void kernel_launch(void* const* d_in, const int* in_sizes, int n_in,
                              void* d_out, int out_size) {
    const float* x       = (const float*)d_in[0];
    const float* norm_w  = (const float*)d_in[1];
    const float* norm_b  = (const float*)d_in[2];
    const float* fus_w1  = (const float*)d_in[21];
    const float* fus_b1  = (const float*)d_in[22];
    const float* fus_w2  = (const float*)d_in[23];
    const float* fus_b2  = (const float*)d_in[24];
    float* out = (float*)d_out;

    const float* in_w [2] = {(const float*)d_in[3],  (const float*)d_in[12]};
    const float* cv_w [2] = {(const float*)d_in[4],  (const float*)d_in[13]};
    const float* cv_b [2] = {(const float*)d_in[5],  (const float*)d_in[14]};
    const float* xp_w [2] = {(const float*)d_in[6],  (const float*)d_in[15]};
    const float* dtp_w[2] = {(const float*)d_in[7],  (const float*)d_in[16]};
    const float* dtp_b[2] = {(const float*)d_in[8],  (const float*)d_in[17]};
    const float* A_log[2] = {(const float*)d_in[9],  (const float*)d_in[18]};
    const float* Dd   [2] = {(const float*)d_in[10], (const float*)d_in[19]};
    const float* out_w[2] = {(const float*)d_in[11], (const float*)d_in[20]};

    __nv_bfloat16* xn16 = sym<__nv_bfloat16>(g_xn16);
    __nv_bfloat16* fused16 = sym<__nv_bfloat16>(g_fused16);
    __nv_bfloat16* h16 = sym<__nv_bfloat16>(g_h16);
    float* xzp   = sym<float>(g_xz);
    float* dblp  = sym<float>(g_dbl);
    float* dtp   = sym<float>(g_dt);
    __nv_bfloat16* uc16p  = sym<__nv_bfloat16>(g_uc16);
    __nv_bfloat16* dbl16p = sym<__nv_bfloat16>(g_dbl16);
    __nv_bfloat16* y16p   = sym<__nv_bfloat16>(g_y16);
    __nv_bfloat16* inwt  = sym<__nv_bfloat16>(g_inwt);
    __nv_bfloat16* xpt   = sym<__nv_bfloat16>(g_xpt);
    __nv_bfloat16* dtpt  = sym<__nv_bfloat16>(g_dtpt);
    __nv_bfloat16* outwt = sym<__nv_bfloat16>(g_outwt);
    __nv_bfloat16* fw1t  = sym<__nv_bfloat16>(g_fw1t);
    __nv_bfloat16* fw2t  = sym<__nv_bfloat16>(g_fw2t);
    int* idx_cw  = sym<int>(g_idx_cw);
    int* idx_ccw = sym<int>(g_idx_ccw);
    const int* idx[2] = {idx_cw, idx_ccw};

    cudaFuncSetAttribute(bf16gemm_kernel,
                         cudaFuncAttributeMaxDynamicSharedMemorySize, GEMM_SMEM);

    spiral_idx_kernel<<<1, LL>>>(idx_cw, idx_ccw);

    WAll wa;
    wa.w[0] = {in_w[0],  inwt,                 CC, 2*CC};
    wa.w[1] = {in_w[1],  inwt + 2*CC*CC,       CC, 2*CC};
    wa.w[2] = {xp_w[0],  xpt,                  CC, DBLC};
    wa.w[3] = {xp_w[1],  xpt + DBLC*CC,        CC, DBLC};
    wa.w[4] = {dtp_w[0], dtpt,                 DR, CC};
    wa.w[5] = {dtp_w[1], dtpt + CC*DR,         DR, CC};
    wa.w[6] = {out_w[0], outwt,                CC, CC};
    wa.w[7] = {out_w[1], outwt + CC*CC,        CC, CC};
    wa.w[8] = {fus_w1,   fw1t,                 2*CC, CC};
    wa.w[9] = {fus_w2,   fw2t,                 CC, CC};
    wt_kernel<<<dim3(48, 48, 10), dim3(32, 8)>>>(wa);

    layernorm_kernel<<<MTOT, 256>>>(x, norm_w, norm_b);

    BrArgs a0, a1;
    // in_proj: xn16 @ inwt -> xz (fp32), spiral gather
    a0 = {xn16, inwt,           nullptr, xzp,              nullptr, idx[0], nullptr, 0};
    a1 = {xn16, inwt + 2*CC*CC, nullptr, xzp + MTOT*2*CC,  nullptr, idx[1], nullptr, 0};
    bf16gemm_kernel<<<dim3(12, 32, 2), 256, GEMM_SMEM>>>(a0, a1, CC, 2*CC, 2*CC, CC, 0, nullptr);

    conv_silu_kernel<<<dim3((MTOT*CC + 255)/256, 2), 256>>>(cv_w[0], cv_b[0], cv_w[1], cv_b[1]);

    // xproj: uc16 @ xpt -> dbl (fp32 + bf16)
    a0 = {uc16p,           xpt,           nullptr, dblp,             dbl16p,             nullptr, nullptr, 0};
    a1 = {uc16p + MTOT*CC, xpt + DBLC*CC, nullptr, dblp + MTOT*DBLC, dbl16p + MTOT*DBLC, nullptr, nullptr, 0};
    bf16gemm_kernel<<<dim3(1, 32, 2), 256, GEMM_SMEM>>>(a0, a1, CC, DBLC, DBLC, CC, 0, nullptr);

    // dt proj + softplus: dbl16[:, :48] @ dtpt -> dt (fp32)
    a0 = {dbl16p,             dtpt,         dtp_b[0], dtp,           nullptr, nullptr, nullptr, 0};
    a1 = {dbl16p + MTOT*DBLC, dtpt + CC*DR, dtp_b[1], dtp + MTOT*CC, nullptr, nullptr, nullptr, 0};
    bf16gemm_kernel<<<dim3(6, 32, 2), 256, GEMM_SMEM>>>(a0, a1, DBLC, CC, CC, DR, 2, nullptr);

    // selective scan (smem-staged)
    scan_kernel<<<dim3(BB * (CC / 8), 2), 128>>>(A_log[0], Dd[0], A_log[1], Dd[1]);

    // out proj with spiral scatter into fused16 concat buffer
    a0 = {y16p,           outwt,         nullptr, nullptr, fused16, nullptr, idx[0], 0};
    a1 = {y16p + MTOT*CC, outwt + CC*CC, nullptr, nullptr, fused16, nullptr, idx[1], CC};
    bf16gemm_kernel<<<dim3(6, 32, 2), 256, GEMM_SMEM>>>(a0, a1, CC, 2*CC, CC, CC, 0, nullptr);

    // fus1: fused16 @ fw1t + b1, GELU -> h16
    a0 = {fused16, fw1t, fus_b1, nullptr, h16, nullptr, nullptr, 0};
    bf16gemm_kernel<<<dim3(6, 32, 1), 256, GEMM_SMEM>>>(a0, a0, 2*CC, CC, CC, 2*CC, 1, nullptr);

    // fus2: h16 @ fw2t + b2 + residual x -> out (fp32)
    a0 = {h16, fw2t, fus_b2, out, nullptr, nullptr, nullptr, 0};
    bf16gemm_kernel<<<dim3(6, 32, 1), 256, GEMM_SMEM>>>(a0, a0, CC, CC, CC, CC, 0, x);
}